// round 16
// baseline (speedup 1.0000x reference)
#include <cuda_runtime.h>
#include <cstdint>

// Problem constants
#define BB   8
#define CCH  256
#define HH   64
#define WW   64
#define HWW  4096
#define OGG  4
#define CG   64
#define KK   9
#define OFFC 72          // 2*9*4 offset channels

// Scratch (static __device__ — no allocation)
__device__ float g_off[BB * OFFC * HWW];          // stage-1 output (offsets)
__device__ float g_w1r[CCH * KK * OFFC];          // repacked w_off: [ci][k][co]
__device__ float g_w2r[OGG * CG * KK * CG];       // repacked w_def: [g][ci][k][co]

// ---------------- f32x2 packed-FMA helpers (B300 FFMA2) ----------------
__device__ __forceinline__ unsigned long long dup_f(float v) {
    unsigned long long r;
    asm("mov.b64 %0, {%1, %1};" : "=l"(r) : "f"(v));
    return r;
}
__device__ __forceinline__ void fma2(unsigned long long& d,
                                     unsigned long long a,
                                     unsigned long long b) {
    asm("fma.rn.f32x2 %0, %1, %2, %0;" : "+l"(d) : "l"(a), "l"(b));
}
__device__ __forceinline__ float2 unpk(unsigned long long v) {
    float2 r;
    asm("mov.b64 {%0, %1}, %2;" : "=f"(r.x), "=f"(r.y) : "l"(v));
    return r;
}

// ---------------- weight repack (runs every replay; trivial cost) ----------------
__global__ void repack_kernel(const float* __restrict__ w_off,
                              const float* __restrict__ w_def) {
    int i = blockIdx.x * 256 + threadIdx.x;
    if (i < CCH * KK * OFFC) {               // 165888
        int co = i % OFFC;
        int k  = (i / OFFC) % KK;
        int ci = i / (OFFC * KK);
        g_w1r[i] = w_off[(co * CCH + ci) * KK + k];
    }
    if (i < OGG * CG * KK * CG) {            // 147456
        int co = i % CG;
        int k  = (i / CG) % KK;
        int t  = i / (CG * KK);
        int ci = t % CG;
        int g  = t / CG;
        g_w2r[i] = w_def[((g * CG + co) * CG + ci) * KK + k];
    }
}

// ---------------- Stage 1: 3x3 conv, Cin=256 -> Cout=72 (offsets) ----------------
// grid = B*H = 512 blocks (one output row each), 288 threads (9 warps).
// warp wq handles co in [wq*8, wq*8+8); lanes = 32 pixel columns, each thread does
// pixels {lane, lane+32}. Weights loaded to SMEM in [ci][k][co] layout (broadcast LDS).
#define S1_THREADS 288
#define S1_CC 16
#define S1_SX   (S1_CC * 3 * 66)            // 3168 floats
#define S1_SW   (S1_CC * KK * OFFC)         // 10368 floats
#define S1_SMEM ((S1_SX + S1_SW) * 4)       // 54144 bytes

__global__ __launch_bounds__(S1_THREADS)
void off_conv_kernel(const float* __restrict__ x, const float* __restrict__ b_off) {
    extern __shared__ float smem[];
    float* sx = smem;               // [ci][3][66] zero-padded cols
    float* sw = smem + S1_SX;       // [ci][k][72]

    int b = blockIdx.x >> 6;
    int h = blockIdx.x & 63;
    int tid  = threadIdx.x;
    int lane = tid & 31;
    int wq   = tid >> 5;            // 0..8
    int co0  = wq * 8;

    unsigned long long acc[2][4] = {};   // [pixel 0/1][co-pair 0..3]

    for (int cc = 0; cc < CCH; cc += S1_CC) {
        // load x rows h-1..h+1 for 16 channels, 66-wide with zero halo
        for (int i = tid; i < S1_SX; i += S1_THREADS) {
            int ci = i / 198;
            int r  = (i % 198) / 66;
            int c  = i % 66;
            int gh = h + r - 1;
            int gc = c - 1;
            float v = 0.f;
            if ((unsigned)gh < 64u && (unsigned)gc < 64u)
                v = x[((b * CCH + cc + ci) * HH + gh) * WW + gc];
            sx[i] = v;
        }
        // load weight chunk (contiguous in repacked layout)
        {
            const float4* wsrc = reinterpret_cast<const float4*>(g_w1r + cc * KK * OFFC);
            float4* wdst = reinterpret_cast<float4*>(sw);
            for (int i = tid; i < S1_SW / 4; i += S1_THREADS) wdst[i] = wsrc[i];
        }
        __syncthreads();

        #pragma unroll 2
        for (int ci = 0; ci < S1_CC; ci++) {
            #pragma unroll
            for (int k = 0; k < 9; k++) {
                const int ky = k / 3, kx = k % 3;
                float xv0 = sx[ci * 198 + ky * 66 + lane + kx];
                float xv1 = sx[ci * 198 + ky * 66 + lane + 32 + kx];
                unsigned long long x0 = dup_f(xv0);
                unsigned long long x1 = dup_f(xv1);
                const ulonglong2* wp =
                    reinterpret_cast<const ulonglong2*>(sw + (ci * 9 + k) * OFFC + co0);
                ulonglong2 wA = wp[0];
                ulonglong2 wB = wp[1];
                fma2(acc[0][0], x0, wA.x); fma2(acc[0][1], x0, wA.y);
                fma2(acc[0][2], x0, wB.x); fma2(acc[0][3], x0, wB.y);
                fma2(acc[1][0], x1, wA.x); fma2(acc[1][1], x1, wA.y);
                fma2(acc[1][2], x1, wB.x); fma2(acc[1][3], x1, wB.y);
            }
        }
        __syncthreads();
    }

    #pragma unroll
    for (int j = 0; j < 4; j++) {
        float2 v0 = unpk(acc[0][j]);
        float2 v1 = unpk(acc[1][j]);
        int coA = co0 + 2 * j;
        int coB = coA + 1;
        float bA = b_off[coA], bB = b_off[coB];
        g_off[((b * OFFC + coA) * HH + h) * WW + lane]      = v0.x + bA;
        g_off[((b * OFFC + coB) * HH + h) * WW + lane]      = v0.y + bB;
        g_off[((b * OFFC + coA) * HH + h) * WW + lane + 32] = v1.x + bA;
        g_off[((b * OFFC + coB) * HH + h) * WW + lane + 32] = v1.y + bB;
    }
}

// ---------------- Stage 2: deformable conv ----------------
// grid = B*OG*(H/2) = 1024 blocks; each block: (b, g, 2 rows = 128 pixels).
// Phase 1: compute per-(tap,pixel) bilinear metadata once (shared across 64 channels).
// Phase 2: per ci-chunk of 8 channels, stage a 12-row x-window in SMEM; samples via LDS
//          (rare global fallback if offset exceeds window); grouped GEMM with FFMA2,
//          weights broadcast per warp from SMEM.
#define S2_THREADS 256
#define PIX   128
#define WIN_R 12
#define SLOW_FLAG (1 << 20)

// smem carve (floats): addr 4608 | wt 4608 | win 6144 | wgt 4608 | smp 2304 = 22272 floats
#define S2_ADDR_OFF 0
#define S2_WT_OFF   4608
#define S2_WIN_OFF  9216
#define S2_WGT_OFF  15360
#define S2_SMP_OFF  19968
#define S2_SMEM     (22272 * 4)    // 89088 bytes

__global__ __launch_bounds__(S2_THREADS)
void deform_kernel(const float* __restrict__ x,
                   const float* __restrict__ b_def,
                   float* __restrict__ out) {
    extern __shared__ float smem[];
    int4*   s_addr = reinterpret_cast<int4*>(smem + S2_ADDR_OFF);   // [K*PIX]
    float4* s_wt   = reinterpret_cast<float4*>(smem + S2_WT_OFF);   // [K*PIX]
    float*  s_win  = smem + S2_WIN_OFF;                              // [8][12*64]
    float*  s_wgt  = smem + S2_WGT_OFF;                              // [8][9][64]
    float*  s_smp  = smem + S2_SMP_OFF;                              // [2][9*128]

    int blk = blockIdx.x;
    int hb = blk & 31;
    int g  = (blk >> 5) & 3;
    int b  = blk >> 7;
    int h0 = hb * 2;
    int tid = threadIdx.x;

    // ---- metadata: bilinear corners + weights per (tap, pixel) ----
    for (int i = tid; i < KK * PIX; i += S2_THREADS) {
        int k = i >> 7;
        int p = i & 127;
        int r = p >> 6;
        int col = p & 63;
        int h = h0 + r;
        const float* ob = g_off + ((b * OFFC + (g * KK + k) * 2) * HH + h) * WW + col;
        float dy = ob[0];
        float dx = ob[HWW];
        float py = dy + (float)(h + (k / 3) - 1);
        float px = dx + (float)(col + (k % 3) - 1);
        float fy0 = floorf(py), fx0 = floorf(px);
        int iy0 = (int)fy0, ix0 = (int)fx0;
        float ly = py - fy0, lx = px - fx0;
        float hy = 1.f - ly, hx = 1.f - lx;
        int iy1 = iy0 + 1, ix1 = ix0 + 1;
        float vy0 = ((unsigned)iy0 < 64u) ? 1.f : 0.f;
        float vy1 = ((unsigned)iy1 < 64u) ? 1.f : 0.f;
        float vx0 = ((unsigned)ix0 < 64u) ? 1.f : 0.f;
        float vx1 = ((unsigned)ix1 < 64u) ? 1.f : 0.f;
        float4 wt;
        wt.x = hy * hx * vy0 * vx0;
        wt.y = hy * lx * vy0 * vx1;
        wt.z = ly * hx * vy1 * vx0;
        wt.w = ly * lx * vy1 * vx1;
        int cy0 = min(max(iy0, 0), 63), cy1 = min(max(iy1, 0), 63);
        int cx0 = min(max(ix0, 0), 63), cx1 = min(max(ix1, 0), 63);
        int4 a;
        bool fast = (cy0 >= h0 - 5) && (cy1 <= h0 + 6);
        if (fast) {
            int s0 = (cy0 - (h0 - 5)) * 64;
            int s1 = (cy1 - (h0 - 5)) * 64;
            a.x = s0 + cx0; a.y = s0 + cx1; a.z = s1 + cx0; a.w = s1 + cx1;
        } else {
            a.x = (cy0 * 64 + cx0) | SLOW_FLAG;
            a.y = cy0 * 64 + cx1;
            a.z = cy1 * 64 + cx0;
            a.w = cy1 * 64 + cx1;
        }
        s_addr[i] = a;
        s_wt[i]   = wt;
    }

    unsigned long long acc[16] = {};      // 32 co per thread, packed pairs
    int p    = tid & 127;
    int half = tid >> 7;
    int co0  = half * 32;
    const float* xg = x + (size_t)(b * CCH + g * CG) * HWW;
    int buf = 0;

    for (int cc = 0; cc < CG; cc += 8) {
        __syncthreads();   // protect s_win/s_wgt reuse across chunks
        // window: 8 channels x 12 rows x 64 cols (float4 loads)
        {
            const float4* xs = reinterpret_cast<const float4*>(xg + cc * HWW);
            float4* wn = reinterpret_cast<float4*>(s_win);
            for (int i = tid; i < 8 * WIN_R * 16; i += S2_THREADS) {
                int ci  = i / (WIN_R * 16);
                int rem = i - ci * (WIN_R * 16);
                int s  = rem >> 4;
                int c4 = rem & 15;
                int gr = h0 - 5 + s;
                float4 v = make_float4(0.f, 0.f, 0.f, 0.f);
                if ((unsigned)gr < 64u) v = xs[ci * (HWW / 4) + gr * 16 + c4];
                wn[ci * (WIN_R * 16) + s * 16 + c4] = v;
            }
        }
        // weight chunk: [8 ci][9 k][64 co], contiguous in repacked layout
        {
            const float4* wsrc =
                reinterpret_cast<const float4*>(g_w2r + (size_t)((g * CG + cc) * KK) * CG);
            float4* wdst = reinterpret_cast<float4*>(s_wgt);
            for (int i = tid; i < (8 * KK * CG) / 4; i += S2_THREADS) wdst[i] = wsrc[i];
        }
        __syncthreads();

        for (int ci = 0; ci < 8; ci++) {
            const float* win = s_win + ci * (WIN_R * 64);
            const float* gx  = xg + (cc + ci) * HWW;
            float* smp = s_smp + buf * (KK * PIX);
            // sampling (LDS fast path, rare LDG fallback)
            for (int i = tid; i < KK * PIX; i += S2_THREADS) {
                int4 a   = s_addr[i];
                float4 w = s_wt[i];
                float v;
                if (a.x < SLOW_FLAG) {
                    v = w.x * win[a.x] + w.y * win[a.y] + w.z * win[a.z] + w.w * win[a.w];
                } else {
                    v = w.x * gx[a.x & (SLOW_FLAG - 1)] + w.y * gx[a.y] +
                        w.z * gx[a.z] + w.w * gx[a.w];
                }
                smp[i] = v;
            }
            __syncthreads();
            // GEMM step: 32 co x 9 taps, weights broadcast per warp
            const float* wrow = s_wgt + ci * (KK * CG);
            #pragma unroll
            for (int k = 0; k < 9; k++) {
                float xv = smp[k * PIX + p];
                unsigned long long xd = dup_f(xv);
                const ulonglong2* wv =
                    reinterpret_cast<const ulonglong2*>(wrow + k * CG + co0);
                #pragma unroll
                for (int j = 0; j < 8; j++) {
                    ulonglong2 ww = wv[j];
                    fma2(acc[2 * j],     xd, ww.x);
                    fma2(acc[2 * j + 1], xd, ww.y);
                }
            }
            buf ^= 1;
        }
    }

    // epilogue
    int r = p >> 6;
    int col = p & 63;
    int h = h0 + r;
    #pragma unroll
    for (int j = 0; j < 16; j++) {
        float2 v = unpk(acc[j]);
        int coA = co0 + 2 * j;
        int coB = coA + 1;
        out[((b * CCH + g * CG + coA) * HH + h) * WW + col] = v.x + b_def[g * CG + coA];
        out[((b * CCH + g * CG + coB) * HH + h) * WW + col] = v.y + b_def[g * CG + coB];
    }
}

// ---------------- launcher ----------------
extern "C" void kernel_launch(void* const* d_in, const int* in_sizes, int n_in,
                              void* d_out, int out_size) {
    const float *x = nullptr, *w_off = nullptr, *b_off = nullptr;
    const float *w_def = nullptr, *b_def = nullptr;
    for (int i = 0; i < n_in; i++) {
        switch (in_sizes[i]) {
            case 8 * 256 * 64 * 64: x     = (const float*)d_in[i]; break;  // 8388608
            case 72 * 256 * 9:      w_off = (const float*)d_in[i]; break;  // 165888
            case 72:                b_off = (const float*)d_in[i]; break;
            case 256 * 64 * 9:      w_def = (const float*)d_in[i]; break;  // 147456
            case 256:               b_def = (const float*)d_in[i]; break;
        }
    }

    cudaFuncSetAttribute(off_conv_kernel,
                         cudaFuncAttributeMaxDynamicSharedMemorySize, S1_SMEM);
    cudaFuncSetAttribute(deform_kernel,
                         cudaFuncAttributeMaxDynamicSharedMemorySize, S2_SMEM);

    repack_kernel<<<(CCH * KK * OFFC + 255) / 256, 256>>>(w_off, w_def);
    off_conv_kernel<<<BB * HH, S1_THREADS, S1_SMEM>>>(x, b_off);
    deform_kernel<<<BB * OGG * (HH / 2), S2_THREADS, S2_SMEM>>>(x, b_def, (float*)d_out);
}